// round 10
// baseline (speedup 1.0000x reference)
#include <cuda_runtime.h>
#include <cuda_fp16.h>
#include <cstdint>

// Problem constants
#define BATCH   2
#define S_LEN   2048
#define D_MODEL 2048
#define NH      16
#define DHEAD   128
#define M_TOK   (BATCH * S_LEN)     // 4096 tokens
#define E3      (3 * NH * DHEAD)    // 6144 qkv features

// Scratch (alloc-free rule: __device__ globals) — fp16 pipeline
__device__ __half g_qkv[(size_t)M_TOK * E3];       // [4096, 6144]
__device__ __half g_attn[(size_t)M_TOK * D_MODEL]; // [4096, 2048]
__device__ __half g_xh[(size_t)M_TOK * D_MODEL];   // half x
__device__ __half g_winh[(size_t)E3 * D_MODEL];    // half w_in
__device__ __half g_wouth[(size_t)D_MODEL * D_MODEL]; // half w_out

// ===========================================================================
// PTX helpers (generic sm_80+ only — toolchain targets plain compute_103)
// ===========================================================================
__device__ __forceinline__ uint32_t smem_u32(const void* p) {
    uint32_t a;
    asm("{ .reg .u64 t; cvta.to.shared.u64 t, %1; cvt.u32.u64 %0, t; }"
        : "=r"(a) : "l"(p));
    return a;
}

__device__ __forceinline__ void ldsm4(uint32_t* r, uint32_t addr) {
    asm volatile("ldmatrix.sync.aligned.m8n8.x4.shared.b16 {%0,%1,%2,%3}, [%4];"
                 : "=r"(r[0]), "=r"(r[1]), "=r"(r[2]), "=r"(r[3]) : "r"(addr));
}

__device__ __forceinline__ void ldsm4t(uint32_t* r, uint32_t addr) {
    asm volatile("ldmatrix.sync.aligned.m8n8.x4.trans.shared.b16 {%0,%1,%2,%3}, [%4];"
                 : "=r"(r[0]), "=r"(r[1]), "=r"(r[2]), "=r"(r[3]) : "r"(addr));
}

// m16n8k16 fp16 MMA, fp32 accumulate
__device__ __forceinline__ void mma_f16(float* c, const uint32_t* a,
                                        uint32_t b0, uint32_t b1) {
    asm volatile(
        "mma.sync.aligned.m16n8k16.row.col.f32.f16.f16.f32 "
        "{%0,%1,%2,%3}, {%4,%5,%6,%7}, {%8,%9}, {%0,%1,%2,%3};"
        : "+f"(c[0]), "+f"(c[1]), "+f"(c[2]), "+f"(c[3])
        : "r"(a[0]), "r"(a[1]), "r"(a[2]), "r"(a[3]), "r"(b0), "r"(b1));
}

__device__ __forceinline__ uint32_t packh2(float a, float b) {
    __half2 h = __floats2half2_rn(a, b);
    return *(const uint32_t*)&h;
}

__device__ __forceinline__ void cp16(uint32_t dst, const void* src) {
    asm volatile("cp.async.cg.shared.global [%0], [%1], 16;"
                 :: "r"(dst), "l"(src));
}
#define CP_COMMIT() asm volatile("cp.async.commit_group;" ::: "memory")
#define CP_WAIT1()  asm volatile("cp.async.wait_group 1;" ::: "memory")
#define CP_WAIT0()  asm volatile("cp.async.wait_group 0;" ::: "memory")

// ===========================================================================
// Fused fp32 -> fp16 conversion (x, w_in, w_out in one launch)
// ===========================================================================
__global__ __launch_bounds__(256)
void cvt_half3(const float* __restrict__ x,  __half* __restrict__ xh,  int n4x,
               const float* __restrict__ wi, __half* __restrict__ wih, int n4wi,
               const float* __restrict__ wo, __half* __restrict__ woh, int n4wo) {
    int i = blockIdx.x * 256 + threadIdx.x;
    const float* s;
    __half* d;
    int k;
    if (i < n4x)                  { s = x;  d = xh;  k = i; }
    else if (i < n4x + n4wi)      { s = wi; d = wih; k = i - n4x; }
    else if (i < n4x + n4wi + n4wo) { s = wo; d = woh; k = i - n4x - n4wi; }
    else return;
    float4 v = ((const float4*)s)[k];
    __half2 h0 = __floats2half2_rn(v.x, v.y);
    __half2 h1 = __floats2half2_rn(v.z, v.w);
    uint2 o;
    o.x = *(const uint32_t*)&h0;
    o.y = *(const uint32_t*)&h1;
    ((uint2*)d)[k] = o;
}

// ===========================================================================
// cp.async 3-stage fp16 GEMM (R8 WIN — unchanged): C[M,N] = A[M,K]*B[N,K]^T
// ===========================================================================
#define NSTAGE 3
#define STAGE_B 32768
#define GEMM_SMEM (NSTAGE * STAGE_B)

template <int OUT_HALF>
__global__ __launch_bounds__(128, 2)
void gemm_mma(const __half* __restrict__ A, const __half* __restrict__ B,
              void* __restrict__ Cv, int M, int N, int K) {
    extern __shared__ unsigned char dsm[];
    const uint32_t sbase = smem_u32(dsm);

    const int tid  = threadIdx.x;
    const int lane = tid & 31;
    const int wid  = tid >> 5;
    const int wm   = wid & 1;
    const int wn   = wid >> 1;
    const int bm   = blockIdx.y * 128;
    const int bn   = blockIdx.x * 128;

    const int lrow = tid >> 3;
    const int lq   = tid & 7;
    const __half* Ag = A + (size_t)(bm + lrow) * K + lq * 8;
    const __half* Bg = B + (size_t)(bn + lrow) * K + lq * 8;
    const uint32_t sq = (uint32_t)((lq ^ (lrow & 7)) * 16);
    const uint32_t stsA = sbase + (uint32_t)lrow * 128 + sq;
    const uint32_t stsB = stsA + 16384;

    const int tA = lane >> 3;
    const int mA = wm * 64 + ((tA & 1) << 3) + (lane & 7);
    const uint32_t kqA = (uint32_t)(tA >> 1);
    const int nB = wn * 64 + ((lane >> 4) << 3) + (lane & 7);
    const uint32_t kqB = (uint32_t)((lane >> 3) & 1);
    const uint32_t swm = (uint32_t)(lane & 7);

    float cacc[4][8][4];
#pragma unroll
    for (int t = 0; t < 4; t++)
#pragma unroll
        for (int n = 0; n < 8; n++)
#pragma unroll
            for (int j = 0; j < 4; j++) cacc[t][n][j] = 0.0f;

    const int NC = K >> 6;

#pragma unroll
    for (int s = 0; s < NSTAGE - 1; s++) {
        const uint32_t so = (uint32_t)s * STAGE_B;
        const int k0 = s * 64;
#pragma unroll
        for (int it = 0; it < 8; it++) {
            cp16(stsA + so + it * 16 * 128u, Ag + k0 + (size_t)it * 16 * K);
            cp16(stsB + so + it * 16 * 128u, Bg + k0 + (size_t)it * 16 * K);
        }
        CP_COMMIT();
    }

    for (int ch = 0; ch < NC; ch++) {
        CP_WAIT1();
        __syncthreads();

        if (ch + NSTAGE - 1 < NC) {
            const uint32_t so = (uint32_t)((ch + NSTAGE - 1) % NSTAGE) * STAGE_B;
            const int k0 = (ch + NSTAGE - 1) * 64;
#pragma unroll
            for (int it = 0; it < 8; it++) {
                cp16(stsA + so + it * 16 * 128u, Ag + k0 + (size_t)it * 16 * K);
                cp16(stsB + so + it * 16 * 128u, Bg + k0 + (size_t)it * 16 * K);
            }
        }
        CP_COMMIT();

        const uint32_t aBase = sbase + (uint32_t)(ch % NSTAGE) * STAGE_B;
        const uint32_t bBase = aBase + 16384;
#pragma unroll
        for (int c = 0; c < 4; c++) {
            uint32_t afr[4][4];
#pragma unroll
            for (int t = 0; t < 4; t++) {
                uint32_t q = (2u * c + kqA) ^ swm;
                ldsm4(afr[t], aBase + (uint32_t)(mA + 16 * t) * 128 + q * 16);
            }
            uint32_t bfr[4][4];
#pragma unroll
            for (int p = 0; p < 4; p++) {
                uint32_t q = (2u * c + kqB) ^ swm;
                ldsm4(bfr[p], bBase + (uint32_t)(nB + 16 * p) * 128 + q * 16);
            }
#pragma unroll
            for (int t = 0; t < 4; t++)
#pragma unroll
                for (int p = 0; p < 4; p++) {
                    mma_f16(cacc[t][2 * p],     afr[t], bfr[p][0], bfr[p][1]);
                    mma_f16(cacc[t][2 * p + 1], afr[t], bfr[p][2], bfr[p][3]);
                }
        }
    }
    CP_WAIT0();

    const int g = lane >> 2;
    const int w2 = (lane & 3) * 2;
#pragma unroll
    for (int t = 0; t < 4; t++) {
        const int row0 = bm + wm * 64 + t * 16 + g;
        const int col0 = bn + wn * 64 + w2;
#pragma unroll
        for (int n = 0; n < 8; n++) {
            if (OUT_HALF) {
                __half* C = (__half*)Cv;
                *(uint32_t*)(C + (size_t)row0 * N + col0 + n * 8) =
                    packh2(cacc[t][n][0], cacc[t][n][1]);
                *(uint32_t*)(C + (size_t)(row0 + 8) * N + col0 + n * 8) =
                    packh2(cacc[t][n][2], cacc[t][n][3]);
            } else {
                float* C = (float*)Cv;
                *(float2*)(C + (size_t)row0 * N + col0 + n * 8) =
                    make_float2(cacc[t][n][0], cacc[t][n][1]);
                *(float2*)(C + (size_t)(row0 + 8) * N + col0 + n * 8) =
                    make_float2(cacc[t][n][2], cacc[t][n][3]);
            }
        }
    }
}

// ===========================================================================
// Flash attention v3 (R9 WIN) + 2 CTAs/SM: fp16 mma, register-resident P,
// trans-ldmatrix V, ONE barrier per kv tile. Smem 96KB -> 2 CTAs = 192KB/SM;
// launch_bounds(256,2) caps regs at 128 so both CTAs fit the register file.
//   Q  128x256B @ 0       (32768)
//   K0  64x256B @ 32768   K1 @ 49152   (16384 each)
//   V0  64x256B @ 65536   V1 @ 81920   (16384 each)
// ===========================================================================
#define FBM 128
#define FBN 64
#define FQ_OFF 0u
#define FK_OFF 32768u
#define FV_OFF 65536u
#define FA_SMEM 98304

__global__ __launch_bounds__(256, 2)
void flash_attn_mma(const __half* __restrict__ qkv, __half* __restrict__ out) {
    extern __shared__ unsigned char fsm[];
    const uint32_t sb = smem_u32(fsm);
    const int tid = threadIdx.x;
    const int lane = tid & 31;
    const int w = tid >> 5;
    const int bh = blockIdx.y;
    const int b = bh >> 4, h = bh & 15;
    const int q0 = ((int)gridDim.x - 1 - (int)blockIdx.x) * FBM;  // heavy first

    const float scale = 0.08838834764831845f;  // 1/sqrt(128)
    const size_t qbase = (size_t)b * S_LEN * E3 + (size_t)h * 384;

    // Prologue: Q (128x16 quads) + K(0) (64x16) + V(0) (64x16)
#pragma unroll
    for (int it = 0; it < 8; it++) {
        int idx = tid + it * 256;
        int r = idx >> 4, kq = idx & 15;
        cp16(sb + FQ_OFF + (uint32_t)r * 256 + (uint32_t)((kq ^ (r & 7)) * 16),
             qkv + qbase + (size_t)(q0 + r) * E3 + kq * 8);
    }
#pragma unroll
    for (int it = 0; it < 4; it++) {
        int idx = tid + it * 256;
        int r = idx >> 4, kq = idx & 15;
        cp16(sb + FK_OFF + (uint32_t)r * 256 + (uint32_t)((kq ^ (r & 7)) * 16),
             qkv + qbase + (size_t)r * E3 + 128 + kq * 8);
    }
#pragma unroll
    for (int it = 0; it < 4; it++) {
        int idx = tid + it * 256;
        int r = idx >> 4, kq = idx & 15;
        cp16(sb + FV_OFF + (uint32_t)r * 256 + (uint32_t)((kq ^ (r & 7)) * 16),
             qkv + qbase + (size_t)r * E3 + 256 + kq * 8);
    }
    CP_COMMIT();

    // ldmatrix per-lane indices
    const int tA = lane >> 3;
    const int rA = ((tA & 1) << 3) + (lane & 7);
    const uint32_t kqA = (uint32_t)(tA >> 1);
    const int rB = ((lane >> 4) << 3) + (lane & 7);
    const uint32_t kqB = (uint32_t)((lane >> 3) & 1);
    const uint32_t swm = (uint32_t)(lane & 7);
    // trans-ldmatrix (V) per-lane: source row within k16 block, dh-quad select
    const int rV  = ((lane >> 3) & 1) * 8 + (lane & 7);
    const int nqV = lane >> 4;
    const int g = lane >> 2;
    const int qw = lane & 3;

    float o_acc[16][4];
#pragma unroll
    for (int n = 0; n < 16; n++)
#pragma unroll
        for (int j = 0; j < 4; j++) o_acc[n][j] = 0.0f;
    float mr0 = -1e30f, mr1 = -1e30f, lr0 = 0.0f, lr1 = 0.0f;

    const int row0g = q0 + w * 16 + g;
    const int row1g = row0g + 8;

    const int nkt = q0 / FBN + 2;
    for (int kb = 0; kb < nkt; kb++) {
        const int k0 = kb * FBN;
        const uint32_t kbuf = sb + FK_OFF + (uint32_t)(kb & 1) * 16384u;
        const uint32_t vbuf = sb + FV_OFF + (uint32_t)(kb & 1) * 16384u;

        CP_WAIT0();
        __syncthreads();   // cp.async data visible; prev tile fully consumed

        if (kb + 1 < nkt) {
            const int kn = k0 + FBN;
            const uint32_t kbufn = sb + FK_OFF + (uint32_t)((kb + 1) & 1) * 16384u;
            const uint32_t vbufn = sb + FV_OFF + (uint32_t)((kb + 1) & 1) * 16384u;
#pragma unroll
            for (int it = 0; it < 4; it++) {
                int idx = tid + it * 256;
                int r = idx >> 4, kq = idx & 15;
                cp16(kbufn + (uint32_t)r * 256 + (uint32_t)((kq ^ (r & 7)) * 16),
                     qkv + qbase + (size_t)(kn + r) * E3 + 128 + kq * 8);
            }
#pragma unroll
            for (int it = 0; it < 4; it++) {
                int idx = tid + it * 256;
                int r = idx >> 4, kq = idx & 15;
                cp16(vbufn + (uint32_t)r * 256 + (uint32_t)((kq ^ (r & 7)) * 16),
                     qkv + qbase + (size_t)(kn + r) * E3 + 256 + kq * 8);
            }
        }
        CP_COMMIT();

        const bool active = (k0 <= q0 + w * 16 + 15);
        if (active) {
            // S = Q * K^T : m16 x n64 x k128 (8 k16-steps)
            float sf[8][4];
#pragma unroll
            for (int n = 0; n < 8; n++)
#pragma unroll
                for (int j = 0; j < 4; j++) sf[n][j] = 0.0f;

#pragma unroll
            for (int c = 0; c < 8; c++) {
                uint32_t af[4];
                uint32_t qa = (2u * c + kqA) ^ swm;
                ldsm4(af, sb + FQ_OFF + (uint32_t)(w * 16 + rA) * 256 + qa * 16);
#pragma unroll
                for (int p = 0; p < 4; p++) {
                    uint32_t bf[4];
                    uint32_t qb = (2u * c + kqB) ^ swm;
                    ldsm4(bf, kbuf + (uint32_t)(p * 16 + rB) * 256 + qb * 16);
                    mma_f16(sf[2 * p],     af, bf[0], bf[1]);
                    mma_f16(sf[2 * p + 1], af, bf[2], bf[3]);
                }
            }

#pragma unroll
            for (int n = 0; n < 8; n++)
#pragma unroll
                for (int j = 0; j < 4; j++) sf[n][j] *= scale;

            if (k0 + FBN - 1 > q0 + w * 16) {
#pragma unroll
                for (int n = 0; n < 8; n++) {
                    int col = k0 + n * 8 + qw * 2;
                    if (col > row0g)     sf[n][0] = -1e30f;
                    if (col + 1 > row0g) sf[n][1] = -1e30f;
                    if (col > row1g)     sf[n][2] = -1e30f;
                    if (col + 1 > row1g) sf[n][3] = -1e30f;
                }
            }

            // Online softmax (rows g and g+8 of the warp band)
            float mx0 = -1e30f, mx1 = -1e30f;
#pragma unroll
            for (int n = 0; n < 8; n++) {
                mx0 = fmaxf(mx0, fmaxf(sf[n][0], sf[n][1]));
                mx1 = fmaxf(mx1, fmaxf(sf[n][2], sf[n][3]));
            }
            mx0 = fmaxf(mx0, __shfl_xor_sync(0xffffffffu, mx0, 1));
            mx0 = fmaxf(mx0, __shfl_xor_sync(0xffffffffu, mx0, 2));
            mx1 = fmaxf(mx1, __shfl_xor_sync(0xffffffffu, mx1, 1));
            mx1 = fmaxf(mx1, __shfl_xor_sync(0xffffffffu, mx1, 2));
            const float mn0 = fmaxf(mr0, mx0);
            const float mn1 = fmaxf(mr1, mx1);
            const float cor0 = __expf(mr0 - mn0);
            const float cor1 = __expf(mr1 - mn1);
            float rs0 = 0.0f, rs1 = 0.0f;
#pragma unroll
            for (int n = 0; n < 8; n++) {
                sf[n][0] = __expf(sf[n][0] - mn0);
                sf[n][1] = __expf(sf[n][1] - mn0);
                sf[n][2] = __expf(sf[n][2] - mn1);
                sf[n][3] = __expf(sf[n][3] - mn1);
                rs0 += sf[n][0] + sf[n][1];
                rs1 += sf[n][2] + sf[n][3];
            }
            rs0 += __shfl_xor_sync(0xffffffffu, rs0, 1);
            rs0 += __shfl_xor_sync(0xffffffffu, rs0, 2);
            rs1 += __shfl_xor_sync(0xffffffffu, rs1, 1);
            rs1 += __shfl_xor_sync(0xffffffffu, rs1, 2);
            lr0 = lr0 * cor0 + rs0;  mr0 = mn0;
            lr1 = lr1 * cor1 + rs1;  mr1 = mn1;
#pragma unroll
            for (int n = 0; n < 16; n++) {
                o_acc[n][0] *= cor0; o_acc[n][1] *= cor0;
                o_acc[n][2] *= cor1; o_acc[n][3] *= cor1;
            }

            // O += P * V : P stays in registers (C-frag == A-frag layout);
            // V via trans-ldmatrix from row-major [s][dh] tile.
#pragma unroll
            for (int c = 0; c < 4; c++) {
                uint32_t af[4];
                af[0] = packh2(sf[2 * c][0],     sf[2 * c][1]);
                af[1] = packh2(sf[2 * c][2],     sf[2 * c][3]);
                af[2] = packh2(sf[2 * c + 1][0], sf[2 * c + 1][1]);
                af[3] = packh2(sf[2 * c + 1][2], sf[2 * c + 1][3]);
                const int rowv = c * 16 + rV;
#pragma unroll
                for (int p = 0; p < 8; p++) {
                    uint32_t bf[4];
                    uint32_t qd = ((uint32_t)(2 * p + nqV)) ^ (uint32_t)(rowv & 7);
                    ldsm4t(bf, vbuf + (uint32_t)rowv * 256 + qd * 16);
                    mma_f16(o_acc[2 * p],     af, bf[0], bf[1]);
                    mma_f16(o_acc[2 * p + 1], af, bf[2], bf[3]);
                }
            }
        }
    }

    // Epilogue: normalize + write half (GEMM2 consumes directly)
    const float inv0 = 1.0f / lr0;
    const float inv1 = 1.0f / lr1;
#pragma unroll
    for (int n = 0; n < 16; n++) {
        const int col = h * DHEAD + n * 8 + qw * 2;
        __half* p0 = out + (size_t)((size_t)b * S_LEN + row0g) * D_MODEL + col;
        __half* p1 = out + (size_t)((size_t)b * S_LEN + row1g) * D_MODEL + col;
        *(uint32_t*)p0 = packh2(o_acc[n][0] * inv0, o_acc[n][1] * inv0);
        *(uint32_t*)p1 = packh2(o_acc[n][2] * inv1, o_acc[n][3] * inv1);
    }
}

// ---------------------------------------------------------------------------
extern "C" void kernel_launch(void* const* d_in, const int* in_sizes, int n_in,
                              void* d_out, int out_size) {
    const float* x     = (const float*)d_in[0];  // [B,S,D]
    const float* w_in  = (const float*)d_in[1];  // [3*H*DH, D]
    const float* w_out = (const float*)d_in[2];  // [D, H*DH]
    float* out = (float*)d_out;                  // [B,S,D]

    __half *qkv, *attn, *xh, *winh, *wouth;
    cudaGetSymbolAddress((void**)&qkv, g_qkv);
    cudaGetSymbolAddress((void**)&attn, g_attn);
    cudaGetSymbolAddress((void**)&xh, g_xh);
    cudaGetSymbolAddress((void**)&winh, g_winh);
    cudaGetSymbolAddress((void**)&wouth, g_wouth);

    cudaFuncSetAttribute(gemm_mma<1>, cudaFuncAttributeMaxDynamicSharedMemorySize,
                         GEMM_SMEM);
    cudaFuncSetAttribute(gemm_mma<0>, cudaFuncAttributeMaxDynamicSharedMemorySize,
                         GEMM_SMEM);
    cudaFuncSetAttribute(flash_attn_mma, cudaFuncAttributeMaxDynamicSharedMemorySize,
                         FA_SMEM);

    // 0) fp16-convert all GEMM operands (single launch)
    const int n4x = M_TOK * D_MODEL / 4;
    const int n4wi = E3 * D_MODEL / 4;
    const int n4wo = D_MODEL * D_MODEL / 4;
    const int n4tot = n4x + n4wi + n4wo;
    cvt_half3<<<(n4tot + 255) / 256, 256>>>(x, xh, n4x, w_in, winh, n4wi,
                                            w_out, wouth, n4wo);

    // 1) QKV projection (half output)
    dim3 g1(E3 / 128, M_TOK / 128);
    gemm_mma<1><<<g1, 128, GEMM_SMEM>>>(xh, winh, qkv, M_TOK, E3, D_MODEL);

    // 2) Causal flash attention (register-P, trans-V, 2 CTAs/SM); half output
    dim3 g2(S_LEN / FBM, BATCH * NH);
    flash_attn_mma<<<g2, 256, FA_SMEM>>>(qkv, attn);

    // 3) Output projection (fp32 output)
    dim3 g3(D_MODEL / 128, M_TOK / 128);
    gemm_mma<0><<<g3, 128, GEMM_SMEM>>>(attn, wouth, out, M_TOK, D_MODEL, D_MODEL);
}

// round 11
// speedup vs baseline: 1.0711x; 1.0711x over previous
#include <cuda_runtime.h>
#include <cuda_fp16.h>
#include <cstdint>

// Problem constants
#define BATCH   2
#define S_LEN   2048
#define D_MODEL 2048
#define NH      16
#define DHEAD   128
#define M_TOK   (BATCH * S_LEN)     // 4096 tokens
#define E3      (3 * NH * DHEAD)    // 6144 qkv features

// Scratch (alloc-free rule: __device__ globals) — fp16 pipeline
__device__ __half g_qkv[(size_t)M_TOK * E3];       // [4096, 6144]
__device__ __half g_attn[(size_t)M_TOK * D_MODEL]; // [4096, 2048]
__device__ __half g_xh[(size_t)M_TOK * D_MODEL];   // half x
__device__ __half g_winh[(size_t)E3 * D_MODEL];    // half w_in
__device__ __half g_wouth[(size_t)D_MODEL * D_MODEL]; // half w_out

// ===========================================================================
// PTX helpers (generic sm_80+ only — toolchain targets plain compute_103)
// ===========================================================================
__device__ __forceinline__ uint32_t smem_u32(const void* p) {
    uint32_t a;
    asm("{ .reg .u64 t; cvta.to.shared.u64 t, %1; cvt.u32.u64 %0, t; }"
        : "=r"(a) : "l"(p));
    return a;
}

__device__ __forceinline__ void ldsm4(uint32_t* r, uint32_t addr) {
    asm volatile("ldmatrix.sync.aligned.m8n8.x4.shared.b16 {%0,%1,%2,%3}, [%4];"
                 : "=r"(r[0]), "=r"(r[1]), "=r"(r[2]), "=r"(r[3]) : "r"(addr));
}

__device__ __forceinline__ void ldsm4t(uint32_t* r, uint32_t addr) {
    asm volatile("ldmatrix.sync.aligned.m8n8.x4.trans.shared.b16 {%0,%1,%2,%3}, [%4];"
                 : "=r"(r[0]), "=r"(r[1]), "=r"(r[2]), "=r"(r[3]) : "r"(addr));
}

// m16n8k16 fp16 MMA, fp32 accumulate
__device__ __forceinline__ void mma_f16(float* c, const uint32_t* a,
                                        uint32_t b0, uint32_t b1) {
    asm volatile(
        "mma.sync.aligned.m16n8k16.row.col.f32.f16.f16.f32 "
        "{%0,%1,%2,%3}, {%4,%5,%6,%7}, {%8,%9}, {%0,%1,%2,%3};"
        : "+f"(c[0]), "+f"(c[1]), "+f"(c[2]), "+f"(c[3])
        : "r"(a[0]), "r"(a[1]), "r"(a[2]), "r"(a[3]), "r"(b0), "r"(b1));
}

__device__ __forceinline__ uint32_t packh2(float a, float b) {
    __half2 h = __floats2half2_rn(a, b);
    return *(const uint32_t*)&h;
}

__device__ __forceinline__ void cp16(uint32_t dst, const void* src) {
    asm volatile("cp.async.cg.shared.global [%0], [%1], 16;"
                 :: "r"(dst), "l"(src));
}
#define CP_COMMIT() asm volatile("cp.async.commit_group;" ::: "memory")
#define CP_WAIT1()  asm volatile("cp.async.wait_group 1;" ::: "memory")
#define CP_WAIT0()  asm volatile("cp.async.wait_group 0;" ::: "memory")

// ===========================================================================
// Fused fp32 -> fp16 conversion (x, w_in, w_out in one launch)
// ===========================================================================
__global__ __launch_bounds__(256)
void cvt_half3(const float* __restrict__ x,  __half* __restrict__ xh,  int n4x,
               const float* __restrict__ wi, __half* __restrict__ wih, int n4wi,
               const float* __restrict__ wo, __half* __restrict__ woh, int n4wo) {
    int i = blockIdx.x * 256 + threadIdx.x;
    const float* s;
    __half* d;
    int k;
    if (i < n4x)                  { s = x;  d = xh;  k = i; }
    else if (i < n4x + n4wi)      { s = wi; d = wih; k = i - n4x; }
    else if (i < n4x + n4wi + n4wo) { s = wo; d = woh; k = i - n4x - n4wi; }
    else return;
    float4 v = ((const float4*)s)[k];
    __half2 h0 = __floats2half2_rn(v.x, v.y);
    __half2 h1 = __floats2half2_rn(v.z, v.w);
    uint2 o;
    o.x = *(const uint32_t*)&h0;
    o.y = *(const uint32_t*)&h1;
    ((uint2*)d)[k] = o;
}

// ===========================================================================
// cp.async 3-stage fp16 GEMM (R8 WIN — unchanged): C[M,N] = A[M,K]*B[N,K]^T
// ===========================================================================
#define NSTAGE 3
#define STAGE_B 32768
#define GEMM_SMEM (NSTAGE * STAGE_B)

template <int OUT_HALF>
__global__ __launch_bounds__(128, 2)
void gemm_mma(const __half* __restrict__ A, const __half* __restrict__ B,
              void* __restrict__ Cv, int M, int N, int K) {
    extern __shared__ unsigned char dsm[];
    const uint32_t sbase = smem_u32(dsm);

    const int tid  = threadIdx.x;
    const int lane = tid & 31;
    const int wid  = tid >> 5;
    const int wm   = wid & 1;
    const int wn   = wid >> 1;
    const int bm   = blockIdx.y * 128;
    const int bn   = blockIdx.x * 128;

    const int lrow = tid >> 3;
    const int lq   = tid & 7;
    const __half* Ag = A + (size_t)(bm + lrow) * K + lq * 8;
    const __half* Bg = B + (size_t)(bn + lrow) * K + lq * 8;
    const uint32_t sq = (uint32_t)((lq ^ (lrow & 7)) * 16);
    const uint32_t stsA = sbase + (uint32_t)lrow * 128 + sq;
    const uint32_t stsB = stsA + 16384;

    const int tA = lane >> 3;
    const int mA = wm * 64 + ((tA & 1) << 3) + (lane & 7);
    const uint32_t kqA = (uint32_t)(tA >> 1);
    const int nB = wn * 64 + ((lane >> 4) << 3) + (lane & 7);
    const uint32_t kqB = (uint32_t)((lane >> 3) & 1);
    const uint32_t swm = (uint32_t)(lane & 7);

    float cacc[4][8][4];
#pragma unroll
    for (int t = 0; t < 4; t++)
#pragma unroll
        for (int n = 0; n < 8; n++)
#pragma unroll
            for (int j = 0; j < 4; j++) cacc[t][n][j] = 0.0f;

    const int NC = K >> 6;

#pragma unroll
    for (int s = 0; s < NSTAGE - 1; s++) {
        const uint32_t so = (uint32_t)s * STAGE_B;
        const int k0 = s * 64;
#pragma unroll
        for (int it = 0; it < 8; it++) {
            cp16(stsA + so + it * 16 * 128u, Ag + k0 + (size_t)it * 16 * K);
            cp16(stsB + so + it * 16 * 128u, Bg + k0 + (size_t)it * 16 * K);
        }
        CP_COMMIT();
    }

    for (int ch = 0; ch < NC; ch++) {
        CP_WAIT1();
        __syncthreads();

        if (ch + NSTAGE - 1 < NC) {
            const uint32_t so = (uint32_t)((ch + NSTAGE - 1) % NSTAGE) * STAGE_B;
            const int k0 = (ch + NSTAGE - 1) * 64;
#pragma unroll
            for (int it = 0; it < 8; it++) {
                cp16(stsA + so + it * 16 * 128u, Ag + k0 + (size_t)it * 16 * K);
                cp16(stsB + so + it * 16 * 128u, Bg + k0 + (size_t)it * 16 * K);
            }
        }
        CP_COMMIT();

        const uint32_t aBase = sbase + (uint32_t)(ch % NSTAGE) * STAGE_B;
        const uint32_t bBase = aBase + 16384;
#pragma unroll
        for (int c = 0; c < 4; c++) {
            uint32_t afr[4][4];
#pragma unroll
            for (int t = 0; t < 4; t++) {
                uint32_t q = (2u * c + kqA) ^ swm;
                ldsm4(afr[t], aBase + (uint32_t)(mA + 16 * t) * 128 + q * 16);
            }
            uint32_t bfr[4][4];
#pragma unroll
            for (int p = 0; p < 4; p++) {
                uint32_t q = (2u * c + kqB) ^ swm;
                ldsm4(bfr[p], bBase + (uint32_t)(nB + 16 * p) * 128 + q * 16);
            }
#pragma unroll
            for (int t = 0; t < 4; t++)
#pragma unroll
                for (int p = 0; p < 4; p++) {
                    mma_f16(cacc[t][2 * p],     afr[t], bfr[p][0], bfr[p][1]);
                    mma_f16(cacc[t][2 * p + 1], afr[t], bfr[p][2], bfr[p][3]);
                }
        }
    }
    CP_WAIT0();

    const int g = lane >> 2;
    const int w2 = (lane & 3) * 2;
#pragma unroll
    for (int t = 0; t < 4; t++) {
        const int row0 = bm + wm * 64 + t * 16 + g;
        const int col0 = bn + wn * 64 + w2;
#pragma unroll
        for (int n = 0; n < 8; n++) {
            if (OUT_HALF) {
                __half* C = (__half*)Cv;
                *(uint32_t*)(C + (size_t)row0 * N + col0 + n * 8) =
                    packh2(cacc[t][n][0], cacc[t][n][1]);
                *(uint32_t*)(C + (size_t)(row0 + 8) * N + col0 + n * 8) =
                    packh2(cacc[t][n][2], cacc[t][n][3]);
            } else {
                float* C = (float*)Cv;
                *(float2*)(C + (size_t)row0 * N + col0 + n * 8) =
                    make_float2(cacc[t][n][0], cacc[t][n][1]);
                *(float2*)(C + (size_t)(row0 + 8) * N + col0 + n * 8) =
                    make_float2(cacc[t][n][2], cacc[t][n][3]);
            }
        }
    }
}

// ===========================================================================
// Flash attention v4: R9 config (1 CTA/SM — 2-CTA spills, proven R10) with
// Q fragments HOISTED INTO REGISTERS (loop-invariant per warp; 32 regs).
// S-loop now issues only K-ldmatrix. One barrier per kv tile.
//   Q  128x256B @ 0       (32768)  [read once into registers]
//   K0  64x256B @ 32768   K1 @ 49152   (16384 each)
//   V0  64x256B @ 65536   V1 @ 81920   (16384 each)
// ===========================================================================
#define FBM 128
#define FBN 64
#define FQ_OFF 0u
#define FK_OFF 32768u
#define FV_OFF 65536u
#define FA_SMEM 98304

__global__ __launch_bounds__(256, 1)
void flash_attn_mma(const __half* __restrict__ qkv, __half* __restrict__ out) {
    extern __shared__ unsigned char fsm[];
    const uint32_t sb = smem_u32(fsm);
    const int tid = threadIdx.x;
    const int lane = tid & 31;
    const int w = tid >> 5;
    const int bh = blockIdx.y;
    const int b = bh >> 4, h = bh & 15;
    const int q0 = ((int)gridDim.x - 1 - (int)blockIdx.x) * FBM;  // heavy first

    const float scale = 0.08838834764831845f;  // 1/sqrt(128)
    const size_t qbase = (size_t)b * S_LEN * E3 + (size_t)h * 384;

    // Prologue: Q (128x16 quads) + K(0) (64x16) + V(0) (64x16)
#pragma unroll
    for (int it = 0; it < 8; it++) {
        int idx = tid + it * 256;
        int r = idx >> 4, kq = idx & 15;
        cp16(sb + FQ_OFF + (uint32_t)r * 256 + (uint32_t)((kq ^ (r & 7)) * 16),
             qkv + qbase + (size_t)(q0 + r) * E3 + kq * 8);
    }
#pragma unroll
    for (int it = 0; it < 4; it++) {
        int idx = tid + it * 256;
        int r = idx >> 4, kq = idx & 15;
        cp16(sb + FK_OFF + (uint32_t)r * 256 + (uint32_t)((kq ^ (r & 7)) * 16),
             qkv + qbase + (size_t)r * E3 + 128 + kq * 8);
    }
#pragma unroll
    for (int it = 0; it < 4; it++) {
        int idx = tid + it * 256;
        int r = idx >> 4, kq = idx & 15;
        cp16(sb + FV_OFF + (uint32_t)r * 256 + (uint32_t)((kq ^ (r & 7)) * 16),
             qkv + qbase + (size_t)r * E3 + 256 + kq * 8);
    }
    CP_COMMIT();

    // ldmatrix per-lane indices
    const int tA = lane >> 3;
    const int rA = ((tA & 1) << 3) + (lane & 7);
    const uint32_t kqA = (uint32_t)(tA >> 1);
    const int rB = ((lane >> 4) << 3) + (lane & 7);
    const uint32_t kqB = (uint32_t)((lane >> 3) & 1);
    const uint32_t swm = (uint32_t)(lane & 7);
    // trans-ldmatrix (V) per-lane: source row within k16 block, dh-quad select
    const int rV  = ((lane >> 3) & 1) * 8 + (lane & 7);
    const int nqV = lane >> 4;
    const int g = lane >> 2;
    const int qw = lane & 3;

    uint32_t qf[8][4];   // Q A-fragments, loop-invariant (loaded at kb==0)
    float o_acc[16][4];
#pragma unroll
    for (int n = 0; n < 16; n++)
#pragma unroll
        for (int j = 0; j < 4; j++) o_acc[n][j] = 0.0f;
    float mr0 = -1e30f, mr1 = -1e30f, lr0 = 0.0f, lr1 = 0.0f;

    const int row0g = q0 + w * 16 + g;
    const int row1g = row0g + 8;

    const int nkt = q0 / FBN + 2;
    for (int kb = 0; kb < nkt; kb++) {
        const int k0 = kb * FBN;
        const uint32_t kbuf = sb + FK_OFF + (uint32_t)(kb & 1) * 16384u;
        const uint32_t vbuf = sb + FV_OFF + (uint32_t)(kb & 1) * 16384u;

        CP_WAIT0();
        __syncthreads();   // cp.async data visible; prev tile fully consumed

        if (kb == 0) {
            // Hoist Q fragments into registers (once per CTA lifetime)
#pragma unroll
            for (int c = 0; c < 8; c++) {
                uint32_t qa = (2u * c + kqA) ^ swm;
                ldsm4(qf[c], sb + FQ_OFF + (uint32_t)(w * 16 + rA) * 256 + qa * 16);
            }
        }

        if (kb + 1 < nkt) {
            const int kn = k0 + FBN;
            const uint32_t kbufn = sb + FK_OFF + (uint32_t)((kb + 1) & 1) * 16384u;
            const uint32_t vbufn = sb + FV_OFF + (uint32_t)((kb + 1) & 1) * 16384u;
#pragma unroll
            for (int it = 0; it < 4; it++) {
                int idx = tid + it * 256;
                int r = idx >> 4, kq = idx & 15;
                cp16(kbufn + (uint32_t)r * 256 + (uint32_t)((kq ^ (r & 7)) * 16),
                     qkv + qbase + (size_t)(kn + r) * E3 + 128 + kq * 8);
            }
#pragma unroll
            for (int it = 0; it < 4; it++) {
                int idx = tid + it * 256;
                int r = idx >> 4, kq = idx & 15;
                cp16(vbufn + (uint32_t)r * 256 + (uint32_t)((kq ^ (r & 7)) * 16),
                     qkv + qbase + (size_t)(kn + r) * E3 + 256 + kq * 8);
            }
        }
        CP_COMMIT();

        const bool active = (k0 <= q0 + w * 16 + 15);
        if (active) {
            // S = Q * K^T : m16 x n64 x k128 (8 k16-steps), Q from registers
            float sf[8][4];
#pragma unroll
            for (int n = 0; n < 8; n++)
#pragma unroll
                for (int j = 0; j < 4; j++) sf[n][j] = 0.0f;

#pragma unroll
            for (int c = 0; c < 8; c++) {
#pragma unroll
                for (int p = 0; p < 4; p++) {
                    uint32_t bf[4];
                    uint32_t qb = (2u * c + kqB) ^ swm;
                    ldsm4(bf, kbuf + (uint32_t)(p * 16 + rB) * 256 + qb * 16);
                    mma_f16(sf[2 * p],     qf[c], bf[0], bf[1]);
                    mma_f16(sf[2 * p + 1], qf[c], bf[2], bf[3]);
                }
            }

#pragma unroll
            for (int n = 0; n < 8; n++)
#pragma unroll
                for (int j = 0; j < 4; j++) sf[n][j] *= scale;

            if (k0 + FBN - 1 > q0 + w * 16) {
#pragma unroll
                for (int n = 0; n < 8; n++) {
                    int col = k0 + n * 8 + qw * 2;
                    if (col > row0g)     sf[n][0] = -1e30f;
                    if (col + 1 > row0g) sf[n][1] = -1e30f;
                    if (col > row1g)     sf[n][2] = -1e30f;
                    if (col + 1 > row1g) sf[n][3] = -1e30f;
                }
            }

            // Online softmax (rows g and g+8 of the warp band)
            float mx0 = -1e30f, mx1 = -1e30f;
#pragma unroll
            for (int n = 0; n < 8; n++) {
                mx0 = fmaxf(mx0, fmaxf(sf[n][0], sf[n][1]));
                mx1 = fmaxf(mx1, fmaxf(sf[n][2], sf[n][3]));
            }
            mx0 = fmaxf(mx0, __shfl_xor_sync(0xffffffffu, mx0, 1));
            mx0 = fmaxf(mx0, __shfl_xor_sync(0xffffffffu, mx0, 2));
            mx1 = fmaxf(mx1, __shfl_xor_sync(0xffffffffu, mx1, 1));
            mx1 = fmaxf(mx1, __shfl_xor_sync(0xffffffffu, mx1, 2));
            const float mn0 = fmaxf(mr0, mx0);
            const float mn1 = fmaxf(mr1, mx1);
            const float cor0 = __expf(mr0 - mn0);
            const float cor1 = __expf(mr1 - mn1);
            float rs0 = 0.0f, rs1 = 0.0f;
#pragma unroll
            for (int n = 0; n < 8; n++) {
                sf[n][0] = __expf(sf[n][0] - mn0);
                sf[n][1] = __expf(sf[n][1] - mn0);
                sf[n][2] = __expf(sf[n][2] - mn1);
                sf[n][3] = __expf(sf[n][3] - mn1);
                rs0 += sf[n][0] + sf[n][1];
                rs1 += sf[n][2] + sf[n][3];
            }
            rs0 += __shfl_xor_sync(0xffffffffu, rs0, 1);
            rs0 += __shfl_xor_sync(0xffffffffu, rs0, 2);
            rs1 += __shfl_xor_sync(0xffffffffu, rs1, 1);
            rs1 += __shfl_xor_sync(0xffffffffu, rs1, 2);
            lr0 = lr0 * cor0 + rs0;  mr0 = mn0;
            lr1 = lr1 * cor1 + rs1;  mr1 = mn1;
#pragma unroll
            for (int n = 0; n < 16; n++) {
                o_acc[n][0] *= cor0; o_acc[n][1] *= cor0;
                o_acc[n][2] *= cor1; o_acc[n][3] *= cor1;
            }

            // O += P * V : P stays in registers (C-frag == A-frag layout);
            // V via trans-ldmatrix from row-major [s][dh] tile.
#pragma unroll
            for (int c = 0; c < 4; c++) {
                uint32_t af[4];
                af[0] = packh2(sf[2 * c][0],     sf[2 * c][1]);
                af[1] = packh2(sf[2 * c][2],     sf[2 * c][3]);
                af[2] = packh2(sf[2 * c + 1][0], sf[2 * c + 1][1]);
                af[3] = packh2(sf[2 * c + 1][2], sf[2 * c + 1][3]);
                const int rowv = c * 16 + rV;
#pragma unroll
                for (int p = 0; p < 8; p++) {
                    uint32_t bf[4];
                    uint32_t qd = ((uint32_t)(2 * p + nqV)) ^ (uint32_t)(rowv & 7);
                    ldsm4t(bf, vbuf + (uint32_t)rowv * 256 + qd * 16);
                    mma_f16(o_acc[2 * p],     af, bf[0], bf[1]);
                    mma_f16(o_acc[2 * p + 1], af, bf[2], bf[3]);
                }
            }
        }
    }

    // Epilogue: normalize + write half (GEMM2 consumes directly)
    const float inv0 = 1.0f / lr0;
    const float inv1 = 1.0f / lr1;
#pragma unroll
    for (int n = 0; n < 16; n++) {
        const int col = h * DHEAD + n * 8 + qw * 2;
        __half* p0 = out + (size_t)((size_t)b * S_LEN + row0g) * D_MODEL + col;
        __half* p1 = out + (size_t)((size_t)b * S_LEN + row1g) * D_MODEL + col;
        *(uint32_t*)p0 = packh2(o_acc[n][0] * inv0, o_acc[n][1] * inv0);
        *(uint32_t*)p1 = packh2(o_acc[n][2] * inv1, o_acc[n][3] * inv1);
    }
}

// ---------------------------------------------------------------------------
extern "C" void kernel_launch(void* const* d_in, const int* in_sizes, int n_in,
                              void* d_out, int out_size) {
    const float* x     = (const float*)d_in[0];  // [B,S,D]
    const float* w_in  = (const float*)d_in[1];  // [3*H*DH, D]
    const float* w_out = (const float*)d_in[2];  // [D, H*DH]
    float* out = (float*)d_out;                  // [B,S,D]

    __half *qkv, *attn, *xh, *winh, *wouth;
    cudaGetSymbolAddress((void**)&qkv, g_qkv);
    cudaGetSymbolAddress((void**)&attn, g_attn);
    cudaGetSymbolAddress((void**)&xh, g_xh);
    cudaGetSymbolAddress((void**)&winh, g_winh);
    cudaGetSymbolAddress((void**)&wouth, g_wouth);

    cudaFuncSetAttribute(gemm_mma<1>, cudaFuncAttributeMaxDynamicSharedMemorySize,
                         GEMM_SMEM);
    cudaFuncSetAttribute(gemm_mma<0>, cudaFuncAttributeMaxDynamicSharedMemorySize,
                         GEMM_SMEM);
    cudaFuncSetAttribute(flash_attn_mma, cudaFuncAttributeMaxDynamicSharedMemorySize,
                         FA_SMEM);

    // 0) fp16-convert all GEMM operands (single launch)
    const int n4x = M_TOK * D_MODEL / 4;
    const int n4wi = E3 * D_MODEL / 4;
    const int n4wo = D_MODEL * D_MODEL / 4;
    const int n4tot = n4x + n4wi + n4wo;
    cvt_half3<<<(n4tot + 255) / 256, 256>>>(x, xh, n4x, w_in, winh, n4wi,
                                            w_out, wouth, n4wo);

    // 1) QKV projection (half output)
    dim3 g1(E3 / 128, M_TOK / 128);
    gemm_mma<1><<<g1, 128, GEMM_SMEM>>>(xh, winh, qkv, M_TOK, E3, D_MODEL);

    // 2) Causal flash attention (register-P, register-Q, trans-V); half out
    dim3 g2(S_LEN / FBM, BATCH * NH);
    flash_attn_mma<<<g2, 256, FA_SMEM>>>(qkv, attn);

    // 3) Output projection (fp32 output)
    dim3 g3(D_MODEL / 128, M_TOK / 128);
    gemm_mma<0><<<g3, 128, GEMM_SMEM>>>(attn, wouth, out, M_TOK, D_MODEL, D_MODEL);
}

// round 12
// speedup vs baseline: 1.0801x; 1.0083x over previous
#include <cuda_runtime.h>
#include <cuda_fp16.h>
#include <cstdint>

// Problem constants
#define BATCH   2
#define S_LEN   2048
#define D_MODEL 2048
#define NH      16
#define DHEAD   128
#define M_TOK   (BATCH * S_LEN)     // 4096 tokens
#define E3      (3 * NH * DHEAD)    // 6144 qkv features

// Scratch (alloc-free rule: __device__ globals) — fp16 pipeline
__device__ __half g_qkv[(size_t)M_TOK * E3];       // [4096, 6144]
__device__ __half g_attn[(size_t)M_TOK * D_MODEL]; // [4096, 2048]
__device__ __half g_xh[(size_t)M_TOK * D_MODEL];   // half x
__device__ __half g_winh[(size_t)E3 * D_MODEL];    // half w_in
__device__ __half g_wouth[(size_t)D_MODEL * D_MODEL]; // half w_out

// ===========================================================================
// PTX helpers (generic sm_80+ only — toolchain targets plain compute_103)
// ===========================================================================
__device__ __forceinline__ uint32_t smem_u32(const void* p) {
    uint32_t a;
    asm("{ .reg .u64 t; cvta.to.shared.u64 t, %1; cvt.u32.u64 %0, t; }"
        : "=r"(a) : "l"(p));
    return a;
}

__device__ __forceinline__ void ldsm4(uint32_t* r, uint32_t addr) {
    asm volatile("ldmatrix.sync.aligned.m8n8.x4.shared.b16 {%0,%1,%2,%3}, [%4];"
                 : "=r"(r[0]), "=r"(r[1]), "=r"(r[2]), "=r"(r[3]) : "r"(addr));
}

__device__ __forceinline__ void ldsm4t(uint32_t* r, uint32_t addr) {
    asm volatile("ldmatrix.sync.aligned.m8n8.x4.trans.shared.b16 {%0,%1,%2,%3}, [%4];"
                 : "=r"(r[0]), "=r"(r[1]), "=r"(r[2]), "=r"(r[3]) : "r"(addr));
}

// m16n8k16 fp16 MMA, fp32 accumulate
__device__ __forceinline__ void mma_f16(float* c, const uint32_t* a,
                                        uint32_t b0, uint32_t b1) {
    asm volatile(
        "mma.sync.aligned.m16n8k16.row.col.f32.f16.f16.f32 "
        "{%0,%1,%2,%3}, {%4,%5,%6,%7}, {%8,%9}, {%0,%1,%2,%3};"
        : "+f"(c[0]), "+f"(c[1]), "+f"(c[2]), "+f"(c[3])
        : "r"(a[0]), "r"(a[1]), "r"(a[2]), "r"(a[3]), "r"(b0), "r"(b1));
}

__device__ __forceinline__ uint32_t packh2(float a, float b) {
    __half2 h = __floats2half2_rn(a, b);
    return *(const uint32_t*)&h;
}

__device__ __forceinline__ void cp16(uint32_t dst, const void* src) {
    asm volatile("cp.async.cg.shared.global [%0], [%1], 16;"
                 :: "r"(dst), "l"(src));
}
#define CP_COMMIT() asm volatile("cp.async.commit_group;" ::: "memory")
#define CP_WAIT1()  asm volatile("cp.async.wait_group 1;" ::: "memory")
#define CP_WAIT0()  asm volatile("cp.async.wait_group 0;" ::: "memory")

// ===========================================================================
// Fused fp32 -> fp16 conversion (x, w_in, w_out in one launch)
// ===========================================================================
__global__ __launch_bounds__(256)
void cvt_half3(const float* __restrict__ x,  __half* __restrict__ xh,  int n4x,
               const float* __restrict__ wi, __half* __restrict__ wih, int n4wi,
               const float* __restrict__ wo, __half* __restrict__ woh, int n4wo) {
    int i = blockIdx.x * 256 + threadIdx.x;
    const float* s;
    __half* d;
    int k;
    if (i < n4x)                  { s = x;  d = xh;  k = i; }
    else if (i < n4x + n4wi)      { s = wi; d = wih; k = i - n4x; }
    else if (i < n4x + n4wi + n4wo) { s = wo; d = woh; k = i - n4x - n4wi; }
    else return;
    float4 v = ((const float4*)s)[k];
    __half2 h0 = __floats2half2_rn(v.x, v.y);
    __half2 h1 = __floats2half2_rn(v.z, v.w);
    uint2 o;
    o.x = *(const uint32_t*)&h0;
    o.y = *(const uint32_t*)&h1;
    ((uint2*)d)[k] = o;
}

// ===========================================================================
// cp.async 3-stage fp16 GEMM (R8 WIN — unchanged): C[M,N] = A[M,K]*B[N,K]^T
// ===========================================================================
#define NSTAGE 3
#define STAGE_B 32768
#define GEMM_SMEM (NSTAGE * STAGE_B)

template <int OUT_HALF>
__global__ __launch_bounds__(128, 2)
void gemm_mma(const __half* __restrict__ A, const __half* __restrict__ B,
              void* __restrict__ Cv, int M, int N, int K) {
    extern __shared__ unsigned char dsm[];
    const uint32_t sbase = smem_u32(dsm);

    const int tid  = threadIdx.x;
    const int lane = tid & 31;
    const int wid  = tid >> 5;
    const int wm   = wid & 1;
    const int wn   = wid >> 1;
    const int bm   = blockIdx.y * 128;
    const int bn   = blockIdx.x * 128;

    const int lrow = tid >> 3;
    const int lq   = tid & 7;
    const __half* Ag = A + (size_t)(bm + lrow) * K + lq * 8;
    const __half* Bg = B + (size_t)(bn + lrow) * K + lq * 8;
    const uint32_t sq = (uint32_t)((lq ^ (lrow & 7)) * 16);
    const uint32_t stsA = sbase + (uint32_t)lrow * 128 + sq;
    const uint32_t stsB = stsA + 16384;

    const int tA = lane >> 3;
    const int mA = wm * 64 + ((tA & 1) << 3) + (lane & 7);
    const uint32_t kqA = (uint32_t)(tA >> 1);
    const int nB = wn * 64 + ((lane >> 4) << 3) + (lane & 7);
    const uint32_t kqB = (uint32_t)((lane >> 3) & 1);
    const uint32_t swm = (uint32_t)(lane & 7);

    float cacc[4][8][4];
#pragma unroll
    for (int t = 0; t < 4; t++)
#pragma unroll
        for (int n = 0; n < 8; n++)
#pragma unroll
            for (int j = 0; j < 4; j++) cacc[t][n][j] = 0.0f;

    const int NC = K >> 6;

#pragma unroll
    for (int s = 0; s < NSTAGE - 1; s++) {
        const uint32_t so = (uint32_t)s * STAGE_B;
        const int k0 = s * 64;
#pragma unroll
        for (int it = 0; it < 8; it++) {
            cp16(stsA + so + it * 16 * 128u, Ag + k0 + (size_t)it * 16 * K);
            cp16(stsB + so + it * 16 * 128u, Bg + k0 + (size_t)it * 16 * K);
        }
        CP_COMMIT();
    }

    for (int ch = 0; ch < NC; ch++) {
        CP_WAIT1();
        __syncthreads();

        if (ch + NSTAGE - 1 < NC) {
            const uint32_t so = (uint32_t)((ch + NSTAGE - 1) % NSTAGE) * STAGE_B;
            const int k0 = (ch + NSTAGE - 1) * 64;
#pragma unroll
            for (int it = 0; it < 8; it++) {
                cp16(stsA + so + it * 16 * 128u, Ag + k0 + (size_t)it * 16 * K);
                cp16(stsB + so + it * 16 * 128u, Bg + k0 + (size_t)it * 16 * K);
            }
        }
        CP_COMMIT();

        const uint32_t aBase = sbase + (uint32_t)(ch % NSTAGE) * STAGE_B;
        const uint32_t bBase = aBase + 16384;
#pragma unroll
        for (int c = 0; c < 4; c++) {
            uint32_t afr[4][4];
#pragma unroll
            for (int t = 0; t < 4; t++) {
                uint32_t q = (2u * c + kqA) ^ swm;
                ldsm4(afr[t], aBase + (uint32_t)(mA + 16 * t) * 128 + q * 16);
            }
            uint32_t bfr[4][4];
#pragma unroll
            for (int p = 0; p < 4; p++) {
                uint32_t q = (2u * c + kqB) ^ swm;
                ldsm4(bfr[p], bBase + (uint32_t)(nB + 16 * p) * 128 + q * 16);
            }
#pragma unroll
            for (int t = 0; t < 4; t++)
#pragma unroll
                for (int p = 0; p < 4; p++) {
                    mma_f16(cacc[t][2 * p],     afr[t], bfr[p][0], bfr[p][1]);
                    mma_f16(cacc[t][2 * p + 1], afr[t], bfr[p][2], bfr[p][3]);
                }
        }
    }
    CP_WAIT0();

    const int g = lane >> 2;
    const int w2 = (lane & 3) * 2;
#pragma unroll
    for (int t = 0; t < 4; t++) {
        const int row0 = bm + wm * 64 + t * 16 + g;
        const int col0 = bn + wn * 64 + w2;
#pragma unroll
        for (int n = 0; n < 8; n++) {
            if (OUT_HALF) {
                __half* C = (__half*)Cv;
                *(uint32_t*)(C + (size_t)row0 * N + col0 + n * 8) =
                    packh2(cacc[t][n][0], cacc[t][n][1]);
                *(uint32_t*)(C + (size_t)(row0 + 8) * N + col0 + n * 8) =
                    packh2(cacc[t][n][2], cacc[t][n][3]);
            } else {
                float* C = (float*)Cv;
                *(float2*)(C + (size_t)row0 * N + col0 + n * 8) =
                    make_float2(cacc[t][n][0], cacc[t][n][1]);
                *(float2*)(C + (size_t)(row0 + 8) * N + col0 + n * 8) =
                    make_float2(cacc[t][n][2], cacc[t][n][3]);
            }
        }
    }
}

// ===========================================================================
// Flash attention v5: FBN=128 smem KV tiles processed as TWO n64 sub-tiles
// per barrier — half the sync rounds of v4, same register footprint.
// Register-Q, register-P, trans-ldmatrix V. 1 CTA/SM (2-CTA spills, R10).
//   Q  128x256B @ 0        (32768)  [read once into registers]
//   K0 128x256B @ 32768    K1 @ 65536   (32768 each)
//   V0 128x256B @ 98304    V1 @ 131072  (32768 each)
// Total 163840.
// ===========================================================================
#define FBM 128
#define FQ_OFF 0u
#define FK_OFF 32768u
#define FV_OFF 98304u
#define FA_SMEM 163840

__global__ __launch_bounds__(256, 1)
void flash_attn_mma(const __half* __restrict__ qkv, __half* __restrict__ out) {
    extern __shared__ unsigned char fsm[];
    const uint32_t sb = smem_u32(fsm);
    const int tid = threadIdx.x;
    const int lane = tid & 31;
    const int w = tid >> 5;
    const int bh = blockIdx.y;
    const int b = bh >> 4, h = bh & 15;
    const int q0 = ((int)gridDim.x - 1 - (int)blockIdx.x) * FBM;  // heavy first

    const float scale = 0.08838834764831845f;  // 1/sqrt(128)
    const size_t qbase = (size_t)b * S_LEN * E3 + (size_t)h * 384;

    // Prologue: Q (128 rows x 16 quads) + K(0) + V(0) (128 rows x 16 quads each)
#pragma unroll
    for (int it = 0; it < 8; it++) {
        int idx = tid + it * 256;
        int r = idx >> 4, kq = idx & 15;
        cp16(sb + FQ_OFF + (uint32_t)r * 256 + (uint32_t)((kq ^ (r & 7)) * 16),
             qkv + qbase + (size_t)(q0 + r) * E3 + kq * 8);
    }
#pragma unroll
    for (int it = 0; it < 8; it++) {
        int idx = tid + it * 256;
        int r = idx >> 4, kq = idx & 15;
        cp16(sb + FK_OFF + (uint32_t)r * 256 + (uint32_t)((kq ^ (r & 7)) * 16),
             qkv + qbase + (size_t)r * E3 + 128 + kq * 8);
    }
#pragma unroll
    for (int it = 0; it < 8; it++) {
        int idx = tid + it * 256;
        int r = idx >> 4, kq = idx & 15;
        cp16(sb + FV_OFF + (uint32_t)r * 256 + (uint32_t)((kq ^ (r & 7)) * 16),
             qkv + qbase + (size_t)r * E3 + 256 + kq * 8);
    }
    CP_COMMIT();

    // ldmatrix per-lane indices
    const int tA = lane >> 3;
    const int rA = ((tA & 1) << 3) + (lane & 7);
    const uint32_t kqA = (uint32_t)(tA >> 1);
    const int rB = ((lane >> 4) << 3) + (lane & 7);
    const uint32_t kqB = (uint32_t)((lane >> 3) & 1);
    const uint32_t swm = (uint32_t)(lane & 7);
    // trans-ldmatrix (V) per-lane: source row within k16 block, dh-quad select
    const int rV  = ((lane >> 3) & 1) * 8 + (lane & 7);
    const int nqV = lane >> 4;
    const int g = lane >> 2;
    const int qw = lane & 3;

    uint32_t qf[8][4];   // Q A-fragments, loop-invariant (loaded at kb==0)
    float o_acc[16][4];
#pragma unroll
    for (int n = 0; n < 16; n++)
#pragma unroll
        for (int j = 0; j < 4; j++) o_acc[n][j] = 0.0f;
    float mr0 = -1e30f, mr1 = -1e30f, lr0 = 0.0f, lr1 = 0.0f;

    const int row0g = q0 + w * 16 + g;
    const int row1g = row0g + 8;

    const int nkt = q0 / FBM + 1;   // 128-key tiles, causal
    for (int kb = 0; kb < nkt; kb++) {
        const int k0 = kb * FBM;
        const uint32_t kbuf = sb + FK_OFF + (uint32_t)(kb & 1) * 32768u;
        const uint32_t vbuf = sb + FV_OFF + (uint32_t)(kb & 1) * 32768u;

        CP_WAIT0();
        __syncthreads();   // tile kb data visible; prev tile fully consumed

        if (kb == 0) {
            // Hoist Q fragments into registers (once per CTA lifetime)
#pragma unroll
            for (int c = 0; c < 8; c++) {
                uint32_t qa = (2u * c + kqA) ^ swm;
                ldsm4(qf[c], sb + FQ_OFF + (uint32_t)(w * 16 + rA) * 256 + qa * 16);
            }
        }

        if (kb + 1 < nkt) {
            const int kn = k0 + FBM;
            const uint32_t kbufn = sb + FK_OFF + (uint32_t)((kb + 1) & 1) * 32768u;
            const uint32_t vbufn = sb + FV_OFF + (uint32_t)((kb + 1) & 1) * 32768u;
#pragma unroll
            for (int it = 0; it < 8; it++) {
                int idx = tid + it * 256;
                int r = idx >> 4, kq = idx & 15;
                cp16(kbufn + (uint32_t)r * 256 + (uint32_t)((kq ^ (r & 7)) * 16),
                     qkv + qbase + (size_t)(kn + r) * E3 + 128 + kq * 8);
            }
#pragma unroll
            for (int it = 0; it < 8; it++) {
                int idx = tid + it * 256;
                int r = idx >> 4, kq = idx & 15;
                cp16(vbufn + (uint32_t)r * 256 + (uint32_t)((kq ^ (r & 7)) * 16),
                     qkv + qbase + (size_t)(kn + r) * E3 + 256 + kq * 8);
            }
        }
        CP_COMMIT();

        // Two n64 sub-tiles per barrier
#pragma unroll
        for (int half = 0; half < 2; half++) {
            const int k0s = k0 + half * 64;
            const uint32_t kbs = kbuf + (uint32_t)half * 16384u;
            const uint32_t vbs = vbuf + (uint32_t)half * 16384u;

            const bool active = (k0s <= q0 + w * 16 + 15);
            if (active) {
                // S = Q * K^T : m16 x n64 x k128, Q from registers
                float sf[8][4];
#pragma unroll
                for (int n = 0; n < 8; n++)
#pragma unroll
                    for (int j = 0; j < 4; j++) sf[n][j] = 0.0f;

#pragma unroll
                for (int c = 0; c < 8; c++) {
#pragma unroll
                    for (int p = 0; p < 4; p++) {
                        uint32_t bf[4];
                        uint32_t qb = (2u * c + kqB) ^ swm;
                        ldsm4(bf, kbs + (uint32_t)(p * 16 + rB) * 256 + qb * 16);
                        mma_f16(sf[2 * p],     qf[c], bf[0], bf[1]);
                        mma_f16(sf[2 * p + 1], qf[c], bf[2], bf[3]);
                    }
                }

#pragma unroll
                for (int n = 0; n < 8; n++)
#pragma unroll
                    for (int j = 0; j < 4; j++) sf[n][j] *= scale;

                if (k0s + 63 > q0 + w * 16) {
#pragma unroll
                    for (int n = 0; n < 8; n++) {
                        int col = k0s + n * 8 + qw * 2;
                        if (col > row0g)     sf[n][0] = -1e30f;
                        if (col + 1 > row0g) sf[n][1] = -1e30f;
                        if (col > row1g)     sf[n][2] = -1e30f;
                        if (col + 1 > row1g) sf[n][3] = -1e30f;
                    }
                }

                // Online softmax (rows g and g+8 of the warp band)
                float mx0 = -1e30f, mx1 = -1e30f;
#pragma unroll
                for (int n = 0; n < 8; n++) {
                    mx0 = fmaxf(mx0, fmaxf(sf[n][0], sf[n][1]));
                    mx1 = fmaxf(mx1, fmaxf(sf[n][2], sf[n][3]));
                }
                mx0 = fmaxf(mx0, __shfl_xor_sync(0xffffffffu, mx0, 1));
                mx0 = fmaxf(mx0, __shfl_xor_sync(0xffffffffu, mx0, 2));
                mx1 = fmaxf(mx1, __shfl_xor_sync(0xffffffffu, mx1, 1));
                mx1 = fmaxf(mx1, __shfl_xor_sync(0xffffffffu, mx1, 2));
                const float mn0 = fmaxf(mr0, mx0);
                const float mn1 = fmaxf(mr1, mx1);
                const float cor0 = __expf(mr0 - mn0);
                const float cor1 = __expf(mr1 - mn1);
                float rs0 = 0.0f, rs1 = 0.0f;
#pragma unroll
                for (int n = 0; n < 8; n++) {
                    sf[n][0] = __expf(sf[n][0] - mn0);
                    sf[n][1] = __expf(sf[n][1] - mn0);
                    sf[n][2] = __expf(sf[n][2] - mn1);
                    sf[n][3] = __expf(sf[n][3] - mn1);
                    rs0 += sf[n][0] + sf[n][1];
                    rs1 += sf[n][2] + sf[n][3];
                }
                rs0 += __shfl_xor_sync(0xffffffffu, rs0, 1);
                rs0 += __shfl_xor_sync(0xffffffffu, rs0, 2);
                rs1 += __shfl_xor_sync(0xffffffffu, rs1, 1);
                rs1 += __shfl_xor_sync(0xffffffffu, rs1, 2);
                lr0 = lr0 * cor0 + rs0;  mr0 = mn0;
                lr1 = lr1 * cor1 + rs1;  mr1 = mn1;
#pragma unroll
                for (int n = 0; n < 16; n++) {
                    o_acc[n][0] *= cor0; o_acc[n][1] *= cor0;
                    o_acc[n][2] *= cor1; o_acc[n][3] *= cor1;
                }

                // O += P * V : P in registers; V via trans-ldmatrix
#pragma unroll
                for (int c = 0; c < 4; c++) {
                    uint32_t af[4];
                    af[0] = packh2(sf[2 * c][0],     sf[2 * c][1]);
                    af[1] = packh2(sf[2 * c][2],     sf[2 * c][3]);
                    af[2] = packh2(sf[2 * c + 1][0], sf[2 * c + 1][1]);
                    af[3] = packh2(sf[2 * c + 1][2], sf[2 * c + 1][3]);
                    const int rowv = c * 16 + rV;
#pragma unroll
                    for (int p = 0; p < 8; p++) {
                        uint32_t bf[4];
                        uint32_t qd = ((uint32_t)(2 * p + nqV)) ^ (uint32_t)(rowv & 7);
                        ldsm4t(bf, vbs + (uint32_t)rowv * 256 + qd * 16);
                        mma_f16(o_acc[2 * p],     af, bf[0], bf[1]);
                        mma_f16(o_acc[2 * p + 1], af, bf[2], bf[3]);
                    }
                }
            }
        }
    }

    // Epilogue: normalize + write half (GEMM2 consumes directly)
    const float inv0 = 1.0f / lr0;
    const float inv1 = 1.0f / lr1;
#pragma unroll
    for (int n = 0; n < 16; n++) {
        const int col = h * DHEAD + n * 8 + qw * 2;
        __half* p0 = out + (size_t)((size_t)b * S_LEN + row0g) * D_MODEL + col;
        __half* p1 = out + (size_t)((size_t)b * S_LEN + row1g) * D_MODEL + col;
        *(uint32_t*)p0 = packh2(o_acc[n][0] * inv0, o_acc[n][1] * inv0);
        *(uint32_t*)p1 = packh2(o_acc[n][2] * inv1, o_acc[n][3] * inv1);
    }
}

// ---------------------------------------------------------------------------
extern "C" void kernel_launch(void* const* d_in, const int* in_sizes, int n_in,
                              void* d_out, int out_size) {
    const float* x     = (const float*)d_in[0];  // [B,S,D]
    const float* w_in  = (const float*)d_in[1];  // [3*H*DH, D]
    const float* w_out = (const float*)d_in[2];  // [D, H*DH]
    float* out = (float*)d_out;                  // [B,S,D]

    __half *qkv, *attn, *xh, *winh, *wouth;
    cudaGetSymbolAddress((void**)&qkv, g_qkv);
    cudaGetSymbolAddress((void**)&attn, g_attn);
    cudaGetSymbolAddress((void**)&xh, g_xh);
    cudaGetSymbolAddress((void**)&winh, g_winh);
    cudaGetSymbolAddress((void**)&wouth, g_wouth);

    cudaFuncSetAttribute(gemm_mma<1>, cudaFuncAttributeMaxDynamicSharedMemorySize,
                         GEMM_SMEM);
    cudaFuncSetAttribute(gemm_mma<0>, cudaFuncAttributeMaxDynamicSharedMemorySize,
                         GEMM_SMEM);
    cudaFuncSetAttribute(flash_attn_mma, cudaFuncAttributeMaxDynamicSharedMemorySize,
                         FA_SMEM);

    // 0) fp16-convert all GEMM operands (single launch)
    const int n4x = M_TOK * D_MODEL / 4;
    const int n4wi = E3 * D_MODEL / 4;
    const int n4wo = D_MODEL * D_MODEL / 4;
    const int n4tot = n4x + n4wi + n4wo;
    cvt_half3<<<(n4tot + 255) / 256, 256>>>(x, xh, n4x, w_in, winh, n4wi,
                                            w_out, wouth, n4wo);

    // 1) QKV projection (half output)
    dim3 g1(E3 / 128, M_TOK / 128);
    gemm_mma<1><<<g1, 128, GEMM_SMEM>>>(xh, winh, qkv, M_TOK, E3, D_MODEL);

    // 2) Causal flash attention (FBN=128 tiles, 2 sub-tiles/barrier)
    dim3 g2(S_LEN / FBM, BATCH * NH);
    flash_attn_mma<<<g2, 256, FA_SMEM>>>(qkv, attn);

    // 3) Output projection (fp32 output)
    dim3 g3(D_MODEL / 128, M_TOK / 128);
    gemm_mma<0><<<g3, 128, GEMM_SMEM>>>(attn, wouth, out, M_TOK, D_MODEL, D_MODEL);
}

// round 13
// speedup vs baseline: 1.1055x; 1.0235x over previous
#include <cuda_runtime.h>
#include <cuda_fp16.h>
#include <cstdint>

// Problem constants
#define BATCH   2
#define S_LEN   2048
#define D_MODEL 2048
#define NH      16
#define DHEAD   128
#define M_TOK   (BATCH * S_LEN)     // 4096 tokens
#define E3      (3 * NH * DHEAD)    // 6144 qkv features

// Scratch (alloc-free rule: __device__ globals) — fp16 pipeline
__device__ __half g_qkv[(size_t)M_TOK * E3];       // [4096, 6144]
__device__ __half g_attn[(size_t)M_TOK * D_MODEL]; // [4096, 2048]
__device__ __half g_xh[(size_t)M_TOK * D_MODEL];   // half x
__device__ __half g_winh[(size_t)E3 * D_MODEL];    // half w_in
__device__ __half g_wouth[(size_t)D_MODEL * D_MODEL]; // half w_out

// ===========================================================================
// PTX helpers (generic sm_80+ only — toolchain targets plain compute_103)
// ===========================================================================
__device__ __forceinline__ uint32_t smem_u32(const void* p) {
    uint32_t a;
    asm("{ .reg .u64 t; cvta.to.shared.u64 t, %1; cvt.u32.u64 %0, t; }"
        : "=r"(a) : "l"(p));
    return a;
}

__device__ __forceinline__ void ldsm4(uint32_t* r, uint32_t addr) {
    asm volatile("ldmatrix.sync.aligned.m8n8.x4.shared.b16 {%0,%1,%2,%3}, [%4];"
                 : "=r"(r[0]), "=r"(r[1]), "=r"(r[2]), "=r"(r[3]) : "r"(addr));
}

__device__ __forceinline__ void ldsm4t(uint32_t* r, uint32_t addr) {
    asm volatile("ldmatrix.sync.aligned.m8n8.x4.trans.shared.b16 {%0,%1,%2,%3}, [%4];"
                 : "=r"(r[0]), "=r"(r[1]), "=r"(r[2]), "=r"(r[3]) : "r"(addr));
}

// m16n8k16 fp16 MMA, fp32 accumulate
__device__ __forceinline__ void mma_f16(float* c, const uint32_t* a,
                                        uint32_t b0, uint32_t b1) {
    asm volatile(
        "mma.sync.aligned.m16n8k16.row.col.f32.f16.f16.f32 "
        "{%0,%1,%2,%3}, {%4,%5,%6,%7}, {%8,%9}, {%0,%1,%2,%3};"
        : "+f"(c[0]), "+f"(c[1]), "+f"(c[2]), "+f"(c[3])
        : "r"(a[0]), "r"(a[1]), "r"(a[2]), "r"(a[3]), "r"(b0), "r"(b1));
}

__device__ __forceinline__ uint32_t packh2(float a, float b) {
    __half2 h = __floats2half2_rn(a, b);
    return *(const uint32_t*)&h;
}

__device__ __forceinline__ void cp16(uint32_t dst, const void* src) {
    asm volatile("cp.async.cg.shared.global [%0], [%1], 16;"
                 :: "r"(dst), "l"(src));
}
#define CP_COMMIT() asm volatile("cp.async.commit_group;" ::: "memory")
#define CP_WAIT1()  asm volatile("cp.async.wait_group 1;" ::: "memory")
#define CP_WAIT0()  asm volatile("cp.async.wait_group 0;" ::: "memory")

// ===========================================================================
// Fused fp32 -> fp16 conversion (x, w_in, w_out in one launch)
// ===========================================================================
__global__ __launch_bounds__(256)
void cvt_half3(const float* __restrict__ x,  __half* __restrict__ xh,  int n4x,
               const float* __restrict__ wi, __half* __restrict__ wih, int n4wi,
               const float* __restrict__ wo, __half* __restrict__ woh, int n4wo) {
    int i = blockIdx.x * 256 + threadIdx.x;
    const float* s;
    __half* d;
    int k;
    if (i < n4x)                  { s = x;  d = xh;  k = i; }
    else if (i < n4x + n4wi)      { s = wi; d = wih; k = i - n4x; }
    else if (i < n4x + n4wi + n4wo) { s = wo; d = woh; k = i - n4x - n4wi; }
    else return;
    float4 v = ((const float4*)s)[k];
    __half2 h0 = __floats2half2_rn(v.x, v.y);
    __half2 h1 = __floats2half2_rn(v.z, v.w);
    uint2 o;
    o.x = *(const uint32_t*)&h0;
    o.y = *(const uint32_t*)&h1;
    ((uint2*)d)[k] = o;
}

// ===========================================================================
// cp.async 3-stage fp16 GEMM (R8 WIN — unchanged): C[M,N] = A[M,K]*B[N,K]^T
// ===========================================================================
#define NSTAGE 3
#define STAGE_B 32768
#define GEMM_SMEM (NSTAGE * STAGE_B)

template <int OUT_HALF>
__global__ __launch_bounds__(128, 2)
void gemm_mma(const __half* __restrict__ A, const __half* __restrict__ B,
              void* __restrict__ Cv, int M, int N, int K) {
    extern __shared__ unsigned char dsm[];
    const uint32_t sbase = smem_u32(dsm);

    const int tid  = threadIdx.x;
    const int lane = tid & 31;
    const int wid  = tid >> 5;
    const int wm   = wid & 1;
    const int wn   = wid >> 1;
    const int bm   = blockIdx.y * 128;
    const int bn   = blockIdx.x * 128;

    const int lrow = tid >> 3;
    const int lq   = tid & 7;
    const __half* Ag = A + (size_t)(bm + lrow) * K + lq * 8;
    const __half* Bg = B + (size_t)(bn + lrow) * K + lq * 8;
    const uint32_t sq = (uint32_t)((lq ^ (lrow & 7)) * 16);
    const uint32_t stsA = sbase + (uint32_t)lrow * 128 + sq;
    const uint32_t stsB = stsA + 16384;

    const int tA = lane >> 3;
    const int mA = wm * 64 + ((tA & 1) << 3) + (lane & 7);
    const uint32_t kqA = (uint32_t)(tA >> 1);
    const int nB = wn * 64 + ((lane >> 4) << 3) + (lane & 7);
    const uint32_t kqB = (uint32_t)((lane >> 3) & 1);
    const uint32_t swm = (uint32_t)(lane & 7);

    float cacc[4][8][4];
#pragma unroll
    for (int t = 0; t < 4; t++)
#pragma unroll
        for (int n = 0; n < 8; n++)
#pragma unroll
            for (int j = 0; j < 4; j++) cacc[t][n][j] = 0.0f;

    const int NC = K >> 6;

#pragma unroll
    for (int s = 0; s < NSTAGE - 1; s++) {
        const uint32_t so = (uint32_t)s * STAGE_B;
        const int k0 = s * 64;
#pragma unroll
        for (int it = 0; it < 8; it++) {
            cp16(stsA + so + it * 16 * 128u, Ag + k0 + (size_t)it * 16 * K);
            cp16(stsB + so + it * 16 * 128u, Bg + k0 + (size_t)it * 16 * K);
        }
        CP_COMMIT();
    }

    for (int ch = 0; ch < NC; ch++) {
        CP_WAIT1();
        __syncthreads();

        if (ch + NSTAGE - 1 < NC) {
            const uint32_t so = (uint32_t)((ch + NSTAGE - 1) % NSTAGE) * STAGE_B;
            const int k0 = (ch + NSTAGE - 1) * 64;
#pragma unroll
            for (int it = 0; it < 8; it++) {
                cp16(stsA + so + it * 16 * 128u, Ag + k0 + (size_t)it * 16 * K);
                cp16(stsB + so + it * 16 * 128u, Bg + k0 + (size_t)it * 16 * K);
            }
        }
        CP_COMMIT();

        const uint32_t aBase = sbase + (uint32_t)(ch % NSTAGE) * STAGE_B;
        const uint32_t bBase = aBase + 16384;
#pragma unroll
        for (int c = 0; c < 4; c++) {
            uint32_t afr[4][4];
#pragma unroll
            for (int t = 0; t < 4; t++) {
                uint32_t q = (2u * c + kqA) ^ swm;
                ldsm4(afr[t], aBase + (uint32_t)(mA + 16 * t) * 128 + q * 16);
            }
            uint32_t bfr[4][4];
#pragma unroll
            for (int p = 0; p < 4; p++) {
                uint32_t q = (2u * c + kqB) ^ swm;
                ldsm4(bfr[p], bBase + (uint32_t)(nB + 16 * p) * 128 + q * 16);
            }
#pragma unroll
            for (int t = 0; t < 4; t++)
#pragma unroll
                for (int p = 0; p < 4; p++) {
                    mma_f16(cacc[t][2 * p],     afr[t], bfr[p][0], bfr[p][1]);
                    mma_f16(cacc[t][2 * p + 1], afr[t], bfr[p][2], bfr[p][3]);
                }
        }
    }
    CP_WAIT0();

    const int g = lane >> 2;
    const int w2 = (lane & 3) * 2;
#pragma unroll
    for (int t = 0; t < 4; t++) {
        const int row0 = bm + wm * 64 + t * 16 + g;
        const int col0 = bn + wn * 64 + w2;
#pragma unroll
        for (int n = 0; n < 8; n++) {
            if (OUT_HALF) {
                __half* C = (__half*)Cv;
                *(uint32_t*)(C + (size_t)row0 * N + col0 + n * 8) =
                    packh2(cacc[t][n][0], cacc[t][n][1]);
                *(uint32_t*)(C + (size_t)(row0 + 8) * N + col0 + n * 8) =
                    packh2(cacc[t][n][2], cacc[t][n][3]);
            } else {
                float* C = (float*)Cv;
                *(float2*)(C + (size_t)row0 * N + col0 + n * 8) =
                    make_float2(cacc[t][n][0], cacc[t][n][1]);
                *(float2*)(C + (size_t)(row0 + 8) * N + col0 + n * 8) =
                    make_float2(cacc[t][n][2], cacc[t][n][3]);
            }
        }
    }
}

// ===========================================================================
// Flash attention v6: FBM=64, 128 threads (4 warps), 2 CTAs/SM.
// Each warp keeps the full m16 x n128 workload (no reg-pressure change vs v4;
// launch_bounds(128,2) caps regs at 256 — no spill, unlike R10's (256,2)).
// Register-Q, register-P, trans-ldmatrix V; FBN=64 double-buffered K/V.
// Smem/CTA: Q 16K @0, K0 @16384, K1 @32768, V0 @49152, V1 @65536 = 80KB.
// 2 CTAs/SM -> barrier/cp-wait bubbles of one CTA hide behind the other.
// Grid: 32 q-tiles x 32 bh = 1024 CTAs, heavy (large q0) first.
// ===========================================================================
#define FBM 64
#define FBN 64
#define FQ_OFF 0u
#define FK_OFF 16384u
#define FV_OFF 49152u
#define FA_SMEM 81920

__global__ __launch_bounds__(128, 2)
void flash_attn_mma(const __half* __restrict__ qkv, __half* __restrict__ out) {
    extern __shared__ unsigned char fsm[];
    const uint32_t sb = smem_u32(fsm);
    const int tid = threadIdx.x;
    const int lane = tid & 31;
    const int w = tid >> 5;       // 0..3
    const int bh = blockIdx.y;
    const int b = bh >> 4, h = bh & 15;
    const int q0 = ((int)gridDim.x - 1 - (int)blockIdx.x) * FBM;  // heavy first

    const float scale = 0.08838834764831845f;  // 1/sqrt(128)
    const size_t qbase = (size_t)b * S_LEN * E3 + (size_t)h * 384;

    // Prologue: Q (64 rows x 16 quads) + K(0) + V(0) — 8 cp16/thread each
#pragma unroll
    for (int it = 0; it < 8; it++) {
        int idx = tid + it * 128;
        int r = idx >> 4, kq = idx & 15;
        cp16(sb + FQ_OFF + (uint32_t)r * 256 + (uint32_t)((kq ^ (r & 7)) * 16),
             qkv + qbase + (size_t)(q0 + r) * E3 + kq * 8);
    }
#pragma unroll
    for (int it = 0; it < 8; it++) {
        int idx = tid + it * 128;
        int r = idx >> 4, kq = idx & 15;
        cp16(sb + FK_OFF + (uint32_t)r * 256 + (uint32_t)((kq ^ (r & 7)) * 16),
             qkv + qbase + (size_t)r * E3 + 128 + kq * 8);
    }
#pragma unroll
    for (int it = 0; it < 8; it++) {
        int idx = tid + it * 128;
        int r = idx >> 4, kq = idx & 15;
        cp16(sb + FV_OFF + (uint32_t)r * 256 + (uint32_t)((kq ^ (r & 7)) * 16),
             qkv + qbase + (size_t)r * E3 + 256 + kq * 8);
    }
    CP_COMMIT();

    // ldmatrix per-lane indices
    const int tA = lane >> 3;
    const int rA = ((tA & 1) << 3) + (lane & 7);
    const uint32_t kqA = (uint32_t)(tA >> 1);
    const int rB = ((lane >> 4) << 3) + (lane & 7);
    const uint32_t kqB = (uint32_t)((lane >> 3) & 1);
    const uint32_t swm = (uint32_t)(lane & 7);
    // trans-ldmatrix (V) per-lane: source row within k16 block, dh-quad select
    const int rV  = ((lane >> 3) & 1) * 8 + (lane & 7);
    const int nqV = lane >> 4;
    const int g = lane >> 2;
    const int qw = lane & 3;

    uint32_t qf[8][4];   // Q A-fragments, loop-invariant (loaded at kb==0)
    float o_acc[16][4];
#pragma unroll
    for (int n = 0; n < 16; n++)
#pragma unroll
        for (int j = 0; j < 4; j++) o_acc[n][j] = 0.0f;
    float mr0 = -1e30f, mr1 = -1e30f, lr0 = 0.0f, lr1 = 0.0f;

    const int row0g = q0 + w * 16 + g;
    const int row1g = row0g + 8;

    const int nkt = q0 / FBN + 1;   // causal: key tiles 0..q0/64
    for (int kb = 0; kb < nkt; kb++) {
        const int k0 = kb * FBN;
        const uint32_t kbuf = sb + FK_OFF + (uint32_t)(kb & 1) * 16384u;
        const uint32_t vbuf = sb + FV_OFF + (uint32_t)(kb & 1) * 16384u;

        CP_WAIT0();
        __syncthreads();   // cp.async data visible; prev tile fully consumed

        if (kb == 0) {
            // Hoist Q fragments into registers (once per CTA lifetime)
#pragma unroll
            for (int c = 0; c < 8; c++) {
                uint32_t qa = (2u * c + kqA) ^ swm;
                ldsm4(qf[c], sb + FQ_OFF + (uint32_t)(w * 16 + rA) * 256 + qa * 16);
            }
        }

        if (kb + 1 < nkt) {
            const int kn = k0 + FBN;
            const uint32_t kbufn = sb + FK_OFF + (uint32_t)((kb + 1) & 1) * 16384u;
            const uint32_t vbufn = sb + FV_OFF + (uint32_t)((kb + 1) & 1) * 16384u;
#pragma unroll
            for (int it = 0; it < 8; it++) {
                int idx = tid + it * 128;
                int r = idx >> 4, kq = idx & 15;
                cp16(kbufn + (uint32_t)r * 256 + (uint32_t)((kq ^ (r & 7)) * 16),
                     qkv + qbase + (size_t)(kn + r) * E3 + 128 + kq * 8);
            }
#pragma unroll
            for (int it = 0; it < 8; it++) {
                int idx = tid + it * 128;
                int r = idx >> 4, kq = idx & 15;
                cp16(vbufn + (uint32_t)r * 256 + (uint32_t)((kq ^ (r & 7)) * 16),
                     qkv + qbase + (size_t)(kn + r) * E3 + 256 + kq * 8);
            }
        }
        CP_COMMIT();

        // S = Q * K^T : m16 x n64 x k128 (8 k16-steps), Q from registers
        float sf[8][4];
#pragma unroll
        for (int n = 0; n < 8; n++)
#pragma unroll
            for (int j = 0; j < 4; j++) sf[n][j] = 0.0f;

#pragma unroll
        for (int c = 0; c < 8; c++) {
#pragma unroll
            for (int p = 0; p < 4; p++) {
                uint32_t bf[4];
                uint32_t qb = (2u * c + kqB) ^ swm;
                ldsm4(bf, kbuf + (uint32_t)(p * 16 + rB) * 256 + qb * 16);
                mma_f16(sf[2 * p],     qf[c], bf[0], bf[1]);
                mma_f16(sf[2 * p + 1], qf[c], bf[2], bf[3]);
            }
        }

#pragma unroll
        for (int n = 0; n < 8; n++)
#pragma unroll
            for (int j = 0; j < 4; j++) sf[n][j] *= scale;

        if (k0 + FBN - 1 > q0 + w * 16) {
#pragma unroll
            for (int n = 0; n < 8; n++) {
                int col = k0 + n * 8 + qw * 2;
                if (col > row0g)     sf[n][0] = -1e30f;
                if (col + 1 > row0g) sf[n][1] = -1e30f;
                if (col > row1g)     sf[n][2] = -1e30f;
                if (col + 1 > row1g) sf[n][3] = -1e30f;
            }
        }

        // Online softmax (rows g and g+8 of the warp band)
        float mx0 = -1e30f, mx1 = -1e30f;
#pragma unroll
        for (int n = 0; n < 8; n++) {
            mx0 = fmaxf(mx0, fmaxf(sf[n][0], sf[n][1]));
            mx1 = fmaxf(mx1, fmaxf(sf[n][2], sf[n][3]));
        }
        mx0 = fmaxf(mx0, __shfl_xor_sync(0xffffffffu, mx0, 1));
        mx0 = fmaxf(mx0, __shfl_xor_sync(0xffffffffu, mx0, 2));
        mx1 = fmaxf(mx1, __shfl_xor_sync(0xffffffffu, mx1, 1));
        mx1 = fmaxf(mx1, __shfl_xor_sync(0xffffffffu, mx1, 2));
        const float mn0 = fmaxf(mr0, mx0);
        const float mn1 = fmaxf(mr1, mx1);
        const float cor0 = __expf(mr0 - mn0);
        const float cor1 = __expf(mr1 - mn1);
        float rs0 = 0.0f, rs1 = 0.0f;
#pragma unroll
        for (int n = 0; n < 8; n++) {
            sf[n][0] = __expf(sf[n][0] - mn0);
            sf[n][1] = __expf(sf[n][1] - mn0);
            sf[n][2] = __expf(sf[n][2] - mn1);
            sf[n][3] = __expf(sf[n][3] - mn1);
            rs0 += sf[n][0] + sf[n][1];
            rs1 += sf[n][2] + sf[n][3];
        }
        rs0 += __shfl_xor_sync(0xffffffffu, rs0, 1);
        rs0 += __shfl_xor_sync(0xffffffffu, rs0, 2);
        rs1 += __shfl_xor_sync(0xffffffffu, rs1, 1);
        rs1 += __shfl_xor_sync(0xffffffffu, rs1, 2);
        lr0 = lr0 * cor0 + rs0;  mr0 = mn0;
        lr1 = lr1 * cor1 + rs1;  mr1 = mn1;
#pragma unroll
        for (int n = 0; n < 16; n++) {
            o_acc[n][0] *= cor0; o_acc[n][1] *= cor0;
            o_acc[n][2] *= cor1; o_acc[n][3] *= cor1;
        }

        // O += P * V : P in registers (C-frag == A-frag layout); trans-V
#pragma unroll
        for (int c = 0; c < 4; c++) {
            uint32_t af[4];
            af[0] = packh2(sf[2 * c][0],     sf[2 * c][1]);
            af[1] = packh2(sf[2 * c][2],     sf[2 * c][3]);
            af[2] = packh2(sf[2 * c + 1][0], sf[2 * c + 1][1]);
            af[3] = packh2(sf[2 * c + 1][2], sf[2 * c + 1][3]);
            const int rowv = c * 16 + rV;
#pragma unroll
            for (int p = 0; p < 8; p++) {
                uint32_t bf[4];
                uint32_t qd = ((uint32_t)(2 * p + nqV)) ^ (uint32_t)(rowv & 7);
                ldsm4t(bf, vbuf + (uint32_t)rowv * 256 + qd * 16);
                mma_f16(o_acc[2 * p],     af, bf[0], bf[1]);
                mma_f16(o_acc[2 * p + 1], af, bf[2], bf[3]);
            }
        }
    }

    // Epilogue: normalize + write half (GEMM2 consumes directly)
    const float inv0 = 1.0f / lr0;
    const float inv1 = 1.0f / lr1;
#pragma unroll
    for (int n = 0; n < 16; n++) {
        const int col = h * DHEAD + n * 8 + qw * 2;
        __half* p0 = out + (size_t)((size_t)b * S_LEN + row0g) * D_MODEL + col;
        __half* p1 = out + (size_t)((size_t)b * S_LEN + row1g) * D_MODEL + col;
        *(uint32_t*)p0 = packh2(o_acc[n][0] * inv0, o_acc[n][1] * inv0);
        *(uint32_t*)p1 = packh2(o_acc[n][2] * inv1, o_acc[n][3] * inv1);
    }
}

// ---------------------------------------------------------------------------
extern "C" void kernel_launch(void* const* d_in, const int* in_sizes, int n_in,
                              void* d_out, int out_size) {
    const float* x     = (const float*)d_in[0];  // [B,S,D]
    const float* w_in  = (const float*)d_in[1];  // [3*H*DH, D]
    const float* w_out = (const float*)d_in[2];  // [D, H*DH]
    float* out = (float*)d_out;                  // [B,S,D]

    __half *qkv, *attn, *xh, *winh, *wouth;
    cudaGetSymbolAddress((void**)&qkv, g_qkv);
    cudaGetSymbolAddress((void**)&attn, g_attn);
    cudaGetSymbolAddress((void**)&xh, g_xh);
    cudaGetSymbolAddress((void**)&winh, g_winh);
    cudaGetSymbolAddress((void**)&wouth, g_wouth);

    cudaFuncSetAttribute(gemm_mma<1>, cudaFuncAttributeMaxDynamicSharedMemorySize,
                         GEMM_SMEM);
    cudaFuncSetAttribute(gemm_mma<0>, cudaFuncAttributeMaxDynamicSharedMemorySize,
                         GEMM_SMEM);
    cudaFuncSetAttribute(flash_attn_mma, cudaFuncAttributeMaxDynamicSharedMemorySize,
                         FA_SMEM);

    // 0) fp16-convert all GEMM operands (single launch)
    const int n4x = M_TOK * D_MODEL / 4;
    const int n4wi = E3 * D_MODEL / 4;
    const int n4wo = D_MODEL * D_MODEL / 4;
    const int n4tot = n4x + n4wi + n4wo;
    cvt_half3<<<(n4tot + 255) / 256, 256>>>(x, xh, n4x, w_in, winh, n4wi,
                                            w_out, wouth, n4wo);

    // 1) QKV projection (half output)
    dim3 g1(E3 / 128, M_TOK / 128);
    gemm_mma<1><<<g1, 128, GEMM_SMEM>>>(xh, winh, qkv, M_TOK, E3, D_MODEL);

    // 2) Causal flash attention (FBM=64, 2 CTAs/SM); half output
    dim3 g2(S_LEN / FBM, BATCH * NH);
    flash_attn_mma<<<g2, 128, FA_SMEM>>>(qkv, attn);

    // 3) Output projection (fp32 output)
    dim3 g3(D_MODEL / 128, M_TOK / 128);
    gemm_mma<0><<<g3, 128, GEMM_SMEM>>>(attn, wouth, out, M_TOK, D_MODEL, D_MODEL);
}